// round 4
// baseline (speedup 1.0000x reference)
#include <cuda_runtime.h>

// Problem constants (fixed shapes from reference_code)
#define E_    3
#define QE_   60000
#define P_    40
#define H_    20
#define NIMG_ 1800
#define Q_    (E_ * QE_)        // 180000 atoms
#define NNZ_  14400000
#define AB    256               // atoms per block
#define NB    704               // ceil(Q_/AB)
#define NW    (AB / 32)         // warps per block

// Scratch (static device globals — sanctioned)
__device__ float g_dE[(size_t)Q_ * P_];        // NEGATED dE/dFP, sorted order, 28.8 MB
__device__ int   g_hist[(size_t)NIMG_ * NB];
__device__ int   g_key_total[NIMG_];
__device__ int   g_key_base[NIMG_];

__device__ __forceinline__ float tanh_fast(float x) {
    float y;
    asm("tanh.approx.f32 %0, %1;" : "=f"(y) : "f"(x));
    return y;
}

// ---------------------------------------------------------------------------
__global__ void k_zero(float* __restrict__ out, int n) {
    int i = blockIdx.x * blockDim.x + threadIdx.x;
    if (i < n) out[i] = 0.0f;
}

// ---------------------------------------------------------------------------
__global__ void k_hist(const int* __restrict__ idx) {
    __shared__ int h[NIMG_];
    for (int k = threadIdx.x; k < NIMG_; k += blockDim.x) h[k] = 0;
    __syncthreads();
    int a = blockIdx.x * AB + threadIdx.x;
    if (a < Q_) atomicAdd(&h[idx[a]], 1);
    __syncthreads();
    for (int k = threadIdx.x; k < NIMG_; k += blockDim.x)
        g_hist[(size_t)k * NB + blockIdx.x] = h[k];
}

// ---------------------------------------------------------------------------
// Per-key exclusive scan over blocks: warp-shuffle 2-level scan.
// ---------------------------------------------------------------------------
__global__ void k_scan_blocks() {
    __shared__ int wsum[32];
    int k = blockIdx.x, t = threadIdx.x;
    int lane = t & 31, w = t >> 5;
    int v = (t < NB) ? g_hist[(size_t)k * NB + t] : 0;
    int s = v;
    #pragma unroll
    for (int o = 1; o < 32; o <<= 1) {
        int x = __shfl_up_sync(0xFFFFFFFFu, s, o);
        if (lane >= o) s += x;
    }
    if (lane == 31) wsum[w] = s;
    __syncthreads();
    if (w == 0) {
        int ws = wsum[lane];
        #pragma unroll
        for (int o = 1; o < 32; o <<= 1) {
            int x = __shfl_up_sync(0xFFFFFFFFu, ws, o);
            if (lane >= o) ws += x;
        }
        wsum[lane] = ws;
    }
    __syncthreads();
    int incl = ((w > 0) ? wsum[w - 1] : 0) + s;
    if (t < NB) g_hist[(size_t)k * NB + t] = incl - v;   // exclusive
    if (t == NB - 1) g_key_total[k] = incl;
}

// ---------------------------------------------------------------------------
// Exclusive scan over 1800 key totals (2 elems/thread, shuffle scan).
// ---------------------------------------------------------------------------
__global__ void k_scan_keys() {
    __shared__ int wsum[32];
    int t = threadIdx.x, lane = t & 31, w = t >> 5;
    int i0 = 2 * t, i1 = 2 * t + 1;
    int v0 = (i0 < NIMG_) ? g_key_total[i0] : 0;
    int v1 = (i1 < NIMG_) ? g_key_total[i1] : 0;
    int p = v0 + v1, s = p;
    #pragma unroll
    for (int o = 1; o < 32; o <<= 1) {
        int x = __shfl_up_sync(0xFFFFFFFFu, s, o);
        if (lane >= o) s += x;
    }
    if (lane == 31) wsum[w] = s;
    __syncthreads();
    if (w == 0) {
        int ws = wsum[lane];
        #pragma unroll
        for (int o = 1; o < 32; o <<= 1) {
            int x = __shfl_up_sync(0xFFFFFFFFu, ws, o);
            if (lane >= o) ws += x;
        }
        wsum[lane] = ws;
    }
    __syncthreads();
    int excl = ((w > 0) ? wsum[w - 1] : 0) + s - p;
    if (i0 < NIMG_) g_key_base[i0] = excl;
    if (i1 < NIMG_) g_key_base[i1] = excl + v0;
}

// ---------------------------------------------------------------------------
// Fused: stable rank + MLP fwd + input-grad + energy scatter.
// Stable local rank now O(1): __match_any_sync intra-warp + warp-ordered
// smem counters (8 barrier rounds) instead of the O(t) smem scan.
// ---------------------------------------------------------------------------
__global__ void __launch_bounds__(AB) k_mlp(
    const float* __restrict__ fps, const float* __restrict__ W1,
    const float* __restrict__ b1,  const float* __restrict__ W2,
    const float* __restrict__ b2,  const float* __restrict__ W3,
    const float* __restrict__ b3,  const int* __restrict__ idx,
    float* __restrict__ energy)
{
    __shared__ float sW1[E_ * P_ * H_];
    __shared__ float sB1[E_ * H_];
    __shared__ float sW2[E_ * H_ * H_];
    __shared__ float sB2[E_ * H_];
    __shared__ float sW3[E_ * H_];
    __shared__ float sB3[E_];
    __shared__ int   scount[NIMG_ + 1];   // per-key running count (stable rank)

    int t = threadIdx.x;
    int lane = t & 31, wid = t >> 5;

    for (int i = t; i < E_ * P_ * H_; i += AB) sW1[i] = W1[i];
    for (int i = t; i < E_ * H_;      i += AB) sB1[i] = b1[i];
    for (int i = t; i < E_ * H_ * H_; i += AB) sW2[i] = W2[i];
    for (int i = t; i < E_ * H_;      i += AB) sB2[i] = b2[i];
    for (int i = t; i < E_ * H_;      i += AB) sW3[i] = W3[i];
    if (t < E_) sB3[t] = b3[t];
    for (int i = t; i < NIMG_ + 1; i += AB) scount[i] = 0;

    int a = blockIdx.x * AB + t;
    int key = (a < Q_) ? idx[a] : -1;
    int kk = (key < 0) ? NIMG_ : key;
    unsigned lt = (1u << lane) - 1u;
    __syncthreads();

    // warp-ordered stable rank: warps take turns (wid order) so earlier
    // threads always reserve earlier slots for the same key.
    int lr = 0;
    #pragma unroll
    for (int w = 0; w < NW; w++) {
        if (wid == w) {
            unsigned m = __match_any_sync(0xFFFFFFFFu, kk);
            int ldr = __ffs(m) - 1;
            int base = 0;
            if (lane == ldr) base = atomicAdd(&scount[kk], __popc(m));
            base = __shfl_sync(m, base, ldr);
            lr = base + __popc(m & lt);
        }
        __syncthreads();
    }
    if (a >= Q_) return;

    int pos = g_key_base[key] + g_hist[(size_t)key * NB + blockIdx.x] + lr;

    int e = a / QE_;
    const float* w1 = sW1 + e * P_ * H_;
    const float* w2 = sW2 + e * H_ * H_;
    const float* w3 = sW3 + e * H_;

    float h1[H_];
    #pragma unroll
    for (int h = 0; h < H_; h++) h1[h] = sB1[e * H_ + h];

    // layer 1: stream x as float4
    const float4* xrow = (const float4*)(fps + (size_t)a * P_);
    #pragma unroll 2
    for (int p4 = 0; p4 < P_ / 4; p4++) {
        float4 x = xrow[p4];
        const float* w1p = w1 + p4 * 4 * H_;
        #pragma unroll
        for (int h = 0; h < H_; h++) {
            float s = fmaf(x.x, w1p[h], h1[h]);
            s = fmaf(x.y, w1p[H_ + h], s);
            s = fmaf(x.z, w1p[2 * H_ + h], s);
            h1[h] = fmaf(x.w, w1p[3 * H_ + h], s);
        }
    }
    #pragma unroll
    for (int h = 0; h < H_; h++) h1[h] = tanh_fast(h1[h]);

    // layer 2
    float g2[H_];
    #pragma unroll
    for (int j = 0; j < H_; j++) {
        float s = sB2[e * H_ + j];
        #pragma unroll
        for (int h = 0; h < H_; h++) s = fmaf(h1[h], w2[h * H_ + j], s);
        g2[j] = tanh_fast(s);
    }

    // layer 3 fwd + backward seed
    float en = sB3[e];
    #pragma unroll
    for (int j = 0; j < H_; j++) {
        float v = g2[j];
        en = fmaf(v, w3[j], en);
        g2[j] = w3[j] * (1.0f - v * v);
    }
    atomicAdd(&energy[key], en);

    // g1 = (W2 @ g2) * (1 - h1^2)
    float g1[H_];
    #pragma unroll
    for (int h = 0; h < H_; h++) {
        float s = 0.0f;
        #pragma unroll
        for (int j = 0; j < H_; j++) s = fmaf(w2[h * H_ + j], g2[j], s);
        g1[h] = s * (1.0f - h1[h] * h1[h]);
    }

    // -dE/dx = -(W1 @ g1), float4 stores into sorted position
    float4* dst = (float4*)(g_dE + (size_t)pos * P_);
    #pragma unroll 2
    for (int p4 = 0; p4 < P_ / 4; p4++) {
        const float* w1p = w1 + p4 * 4 * H_;
        float4 o;
        float s0 = 0, s1 = 0, s2 = 0, s3 = 0;
        #pragma unroll
        for (int h = 0; h < H_; h++) {
            s0 = fmaf(w1p[h],          g1[h], s0);
            s1 = fmaf(w1p[H_ + h],     g1[h], s1);
            s2 = fmaf(w1p[2 * H_ + h], g1[h], s2);
            s3 = fmaf(w1p[3 * H_ + h], g1[h], s3);
        }
        o.x = -s0; o.y = -s1; o.z = -s2; o.w = -s3;
        dst[p4] = o;
    }
}

// ---------------------------------------------------------------------------
// Sparse COO transpose-matvec: force[col] += val * (-dE_sorted[row]).
// 4 int4-groups (16 nnz) per thread, coalesced k*blockDim strides:
// 12 LDG.128 streams + 16 independent L2 gathers in flight per thread.
// ---------------------------------------------------------------------------
#define SGRP 4
__global__ void __launch_bounds__(256) k_scatter(
    const int4* __restrict__ rows, const int4* __restrict__ cols,
    const float4* __restrict__ vals, float* __restrict__ force)
{
    const int NG = NNZ_ / 4;                       // 3.6M int4 groups
    int base = blockIdx.x * (256 * SGRP) + threadIdx.x;

    int4   r[SGRP], c[SGRP];
    float4 v[SGRP];
    bool   ok[SGRP];
    #pragma unroll
    for (int k = 0; k < SGRP; k++) {
        int i = base + k * 256;
        ok[k] = (i < NG);
        if (ok[k]) {
            r[k] = __ldcs(&rows[i]);
            c[k] = __ldcs(&cols[i]);
            v[k] = __ldcs(&vals[i]);
        }
    }
    float d[SGRP][4];
    #pragma unroll
    for (int k = 0; k < SGRP; k++) {
        if (ok[k]) {
            d[k][0] = __ldg(&g_dE[r[k].x]);
            d[k][1] = __ldg(&g_dE[r[k].y]);
            d[k][2] = __ldg(&g_dE[r[k].z]);
            d[k][3] = __ldg(&g_dE[r[k].w]);
        }
    }
    #pragma unroll
    for (int k = 0; k < SGRP; k++) {
        if (ok[k]) {
            atomicAdd(&force[c[k].x], v[k].x * d[k][0]);
            atomicAdd(&force[c[k].y], v[k].y * d[k][1]);
            atomicAdd(&force[c[k].z], v[k].z * d[k][2]);
            atomicAdd(&force[c[k].w], v[k].w * d[k][3]);
        }
    }
}

// ---------------------------------------------------------------------------
extern "C" void kernel_launch(void* const* d_in, const int* in_sizes, int n_in,
                              void* d_out, int out_size)
{
    const float* fps       = (const float*)d_in[0];
    const float* W1        = (const float*)d_in[1];
    const float* b1        = (const float*)d_in[2];
    const float* W2        = (const float*)d_in[3];
    const float* b2        = (const float*)d_in[4];
    const float* W3        = (const float*)d_in[5];
    const float* b3        = (const float*)d_in[6];
    const int*   image_idx = (const int*)d_in[7];
    const int*   fp_rows   = (const int*)d_in[8];
    const int*   fp_cols   = (const int*)d_in[9];
    const float* fp_vals   = (const float*)d_in[10];

    float* out    = (float*)d_out;
    float* energy = out;               // [NIMG, 1]
    float* force  = out + NIMG_;       // [Q, 3] flattened

    k_zero<<<(out_size + 255) / 256, 256>>>(out, out_size);

    k_hist<<<NB, AB>>>(image_idx);
    k_scan_blocks<<<NIMG_, 1024>>>();
    k_scan_keys<<<1, 1024>>>();

    k_mlp<<<NB, AB>>>(fps, W1, b1, W2, b2, W3, b3, image_idx, energy);

    const int ngrp = NNZ_ / 4;
    k_scatter<<<(ngrp + 256 * SGRP - 1) / (256 * SGRP), 256>>>(
        (const int4*)fp_rows, (const int4*)fp_cols, (const float4*)fp_vals, force);
}

// round 5
// speedup vs baseline: 1.0720x; 1.0720x over previous
#include <cuda_runtime.h>

// Problem constants (fixed shapes from reference_code)
#define E_    3
#define QE_   60000
#define P_    40
#define H_    20
#define NIMG_ 1800
#define Q_    (E_ * QE_)        // 180000 atoms
#define NNZ_  14400000
#define AB    256               // atoms per block
#define NB    704               // ceil(Q_/AB)
#define NW    (AB / 32)         // warps per block

// Scratch (static device globals — sanctioned)
__device__ float g_dE[(size_t)Q_ * P_];        // NEGATED dE/dFP, sorted order, 28.8 MB
__device__ int   g_hist[(size_t)NIMG_ * NB];
__device__ int   g_key_total[NIMG_];
__device__ int   g_key_base[NIMG_];

__device__ __forceinline__ float tanh_fast(float x) {
    float y;
    asm("tanh.approx.f32 %0, %1;" : "=f"(y) : "f"(x));
    return y;
}

// ---------------------------------------------------------------------------
__global__ void k_zero(float* __restrict__ out, int n) {
    int i = blockIdx.x * blockDim.x + threadIdx.x;
    if (i < n) out[i] = 0.0f;
}

// ---------------------------------------------------------------------------
__global__ void k_hist(const int* __restrict__ idx) {
    __shared__ int h[NIMG_];
    for (int k = threadIdx.x; k < NIMG_; k += blockDim.x) h[k] = 0;
    __syncthreads();
    int a = blockIdx.x * AB + threadIdx.x;
    if (a < Q_) atomicAdd(&h[idx[a]], 1);
    __syncthreads();
    for (int k = threadIdx.x; k < NIMG_; k += blockDim.x)
        g_hist[(size_t)k * NB + blockIdx.x] = h[k];
}

// ---------------------------------------------------------------------------
// Per-key exclusive scan over blocks: warp-shuffle 2-level scan.
// ---------------------------------------------------------------------------
__global__ void k_scan_blocks() {
    __shared__ int wsum[32];
    int k = blockIdx.x, t = threadIdx.x;
    int lane = t & 31, w = t >> 5;
    int v = (t < NB) ? g_hist[(size_t)k * NB + t] : 0;
    int s = v;
    #pragma unroll
    for (int o = 1; o < 32; o <<= 1) {
        int x = __shfl_up_sync(0xFFFFFFFFu, s, o);
        if (lane >= o) s += x;
    }
    if (lane == 31) wsum[w] = s;
    __syncthreads();
    if (w == 0) {
        int ws = wsum[lane];
        #pragma unroll
        for (int o = 1; o < 32; o <<= 1) {
            int x = __shfl_up_sync(0xFFFFFFFFu, ws, o);
            if (lane >= o) ws += x;
        }
        wsum[lane] = ws;
    }
    __syncthreads();
    int incl = ((w > 0) ? wsum[w - 1] : 0) + s;
    if (t < NB) g_hist[(size_t)k * NB + t] = incl - v;   // exclusive
    if (t == NB - 1) g_key_total[k] = incl;
}

// ---------------------------------------------------------------------------
// Exclusive scan over 1800 key totals (2 elems/thread, shuffle scan).
// ---------------------------------------------------------------------------
__global__ void k_scan_keys() {
    __shared__ int wsum[32];
    int t = threadIdx.x, lane = t & 31, w = t >> 5;
    int i0 = 2 * t, i1 = 2 * t + 1;
    int v0 = (i0 < NIMG_) ? g_key_total[i0] : 0;
    int v1 = (i1 < NIMG_) ? g_key_total[i1] : 0;
    int p = v0 + v1, s = p;
    #pragma unroll
    for (int o = 1; o < 32; o <<= 1) {
        int x = __shfl_up_sync(0xFFFFFFFFu, s, o);
        if (lane >= o) s += x;
    }
    if (lane == 31) wsum[w] = s;
    __syncthreads();
    if (w == 0) {
        int ws = wsum[lane];
        #pragma unroll
        for (int o = 1; o < 32; o <<= 1) {
            int x = __shfl_up_sync(0xFFFFFFFFu, ws, o);
            if (lane >= o) ws += x;
        }
        wsum[lane] = ws;
    }
    __syncthreads();
    int excl = ((w > 0) ? wsum[w - 1] : 0) + s - p;
    if (i0 < NIMG_) g_key_base[i0] = excl;
    if (i1 < NIMG_) g_key_base[i1] = excl + v0;
}

// ---------------------------------------------------------------------------
// Fused: stable rank + MLP fwd + input-grad + energy scatter.
// Stable local rank O(1): __match_any_sync intra-warp + warp-ordered smem
// counters (warps take turns in wid order -> stability preserved).
// ---------------------------------------------------------------------------
__global__ void __launch_bounds__(AB) k_mlp(
    const float* __restrict__ fps, const float* __restrict__ W1,
    const float* __restrict__ b1,  const float* __restrict__ W2,
    const float* __restrict__ b2,  const float* __restrict__ W3,
    const float* __restrict__ b3,  const int* __restrict__ idx,
    float* __restrict__ energy)
{
    __shared__ float sW1[E_ * P_ * H_];
    __shared__ float sB1[E_ * H_];
    __shared__ float sW2[E_ * H_ * H_];
    __shared__ float sB2[E_ * H_];
    __shared__ float sW3[E_ * H_];
    __shared__ float sB3[E_];
    __shared__ int   scount[NIMG_ + 1];   // per-key running count (stable rank)

    int t = threadIdx.x;
    int lane = t & 31, wid = t >> 5;

    for (int i = t; i < E_ * P_ * H_; i += AB) sW1[i] = W1[i];
    for (int i = t; i < E_ * H_;      i += AB) sB1[i] = b1[i];
    for (int i = t; i < E_ * H_ * H_; i += AB) sW2[i] = W2[i];
    for (int i = t; i < E_ * H_;      i += AB) sB2[i] = b2[i];
    for (int i = t; i < E_ * H_;      i += AB) sW3[i] = W3[i];
    if (t < E_) sB3[t] = b3[t];
    for (int i = t; i < NIMG_ + 1; i += AB) scount[i] = 0;

    int a = blockIdx.x * AB + t;
    int key = (a < Q_) ? idx[a] : -1;
    int kk = (key < 0) ? NIMG_ : key;
    unsigned lt = (1u << lane) - 1u;
    __syncthreads();

    // warp-ordered stable rank
    int lr = 0;
    #pragma unroll
    for (int w = 0; w < NW; w++) {
        if (wid == w) {
            unsigned m = __match_any_sync(0xFFFFFFFFu, kk);
            int ldr = __ffs(m) - 1;
            int base = 0;
            if (lane == ldr) base = atomicAdd(&scount[kk], __popc(m));
            base = __shfl_sync(m, base, ldr);
            lr = base + __popc(m & lt);
        }
        __syncthreads();
    }
    if (a >= Q_) return;

    int pos = g_key_base[key] + g_hist[(size_t)key * NB + blockIdx.x] + lr;

    int e = a / QE_;
    const float* w1 = sW1 + e * P_ * H_;
    const float* w2 = sW2 + e * H_ * H_;
    const float* w3 = sW3 + e * H_;

    float h1[H_];
    #pragma unroll
    for (int h = 0; h < H_; h++) h1[h] = sB1[e * H_ + h];

    // layer 1: stream x as float4
    const float4* xrow = (const float4*)(fps + (size_t)a * P_);
    #pragma unroll 2
    for (int p4 = 0; p4 < P_ / 4; p4++) {
        float4 x = xrow[p4];
        const float* w1p = w1 + p4 * 4 * H_;
        #pragma unroll
        for (int h = 0; h < H_; h++) {
            float s = fmaf(x.x, w1p[h], h1[h]);
            s = fmaf(x.y, w1p[H_ + h], s);
            s = fmaf(x.z, w1p[2 * H_ + h], s);
            h1[h] = fmaf(x.w, w1p[3 * H_ + h], s);
        }
    }
    #pragma unroll
    for (int h = 0; h < H_; h++) h1[h] = tanh_fast(h1[h]);

    // layer 2
    float g2[H_];
    #pragma unroll
    for (int j = 0; j < H_; j++) {
        float s = sB2[e * H_ + j];
        #pragma unroll
        for (int h = 0; h < H_; h++) s = fmaf(h1[h], w2[h * H_ + j], s);
        g2[j] = tanh_fast(s);
    }

    // layer 3 fwd + backward seed
    float en = sB3[e];
    #pragma unroll
    for (int j = 0; j < H_; j++) {
        float v = g2[j];
        en = fmaf(v, w3[j], en);
        g2[j] = w3[j] * (1.0f - v * v);
    }
    atomicAdd(&energy[key], en);

    // g1 = (W2 @ g2) * (1 - h1^2)
    float g1[H_];
    #pragma unroll
    for (int h = 0; h < H_; h++) {
        float s = 0.0f;
        #pragma unroll
        for (int j = 0; j < H_; j++) s = fmaf(w2[h * H_ + j], g2[j], s);
        g1[h] = s * (1.0f - h1[h] * h1[h]);
    }

    // -dE/dx = -(W1 @ g1), float4 stores into sorted position
    float4* dst = (float4*)(g_dE + (size_t)pos * P_);
    #pragma unroll 2
    for (int p4 = 0; p4 < P_ / 4; p4++) {
        const float* w1p = w1 + p4 * 4 * H_;
        float4 o;
        float s0 = 0, s1 = 0, s2 = 0, s3 = 0;
        #pragma unroll
        for (int h = 0; h < H_; h++) {
            s0 = fmaf(w1p[h],          g1[h], s0);
            s1 = fmaf(w1p[H_ + h],     g1[h], s1);
            s2 = fmaf(w1p[2 * H_ + h], g1[h], s2);
            s3 = fmaf(w1p[3 * H_ + h], g1[h], s3);
        }
        o.x = -s0; o.y = -s1; o.z = -s2; o.w = -s3;
        dst[p4] = o;
    }
}

// ---------------------------------------------------------------------------
// Sparse COO transpose-matvec (R3 form — known good): one int4-group/thread,
// __ldcs streaming on COO arrays so g_dE + force stay L2-resident.
// ---------------------------------------------------------------------------
__global__ void k_scatter(const int4* __restrict__ rows,
                          const int4* __restrict__ cols,
                          const float4* __restrict__ vals,
                          float* __restrict__ force)
{
    int i = blockIdx.x * blockDim.x + threadIdx.x;
    if (i >= NNZ_ / 4) return;
    int4   r = __ldcs(&rows[i]);
    int4   c = __ldcs(&cols[i]);
    float4 v = __ldcs(&vals[i]);
    float d0 = __ldg(&g_dE[r.x]);
    float d1 = __ldg(&g_dE[r.y]);
    float d2 = __ldg(&g_dE[r.z]);
    float d3 = __ldg(&g_dE[r.w]);
    atomicAdd(&force[c.x], v.x * d0);
    atomicAdd(&force[c.y], v.y * d1);
    atomicAdd(&force[c.z], v.z * d2);
    atomicAdd(&force[c.w], v.w * d3);
}

// ---------------------------------------------------------------------------
extern "C" void kernel_launch(void* const* d_in, const int* in_sizes, int n_in,
                              void* d_out, int out_size)
{
    const float* fps       = (const float*)d_in[0];
    const float* W1        = (const float*)d_in[1];
    const float* b1        = (const float*)d_in[2];
    const float* W2        = (const float*)d_in[3];
    const float* b2        = (const float*)d_in[4];
    const float* W3        = (const float*)d_in[5];
    const float* b3        = (const float*)d_in[6];
    const int*   image_idx = (const int*)d_in[7];
    const int*   fp_rows   = (const int*)d_in[8];
    const int*   fp_cols   = (const int*)d_in[9];
    const float* fp_vals   = (const float*)d_in[10];

    float* out    = (float*)d_out;
    float* energy = out;               // [NIMG, 1]
    float* force  = out + NIMG_;       // [Q, 3] flattened

    k_zero<<<(out_size + 255) / 256, 256>>>(out, out_size);

    k_hist<<<NB, AB>>>(image_idx);
    k_scan_blocks<<<NIMG_, 1024>>>();
    k_scan_keys<<<1, 1024>>>();

    k_mlp<<<NB, AB>>>(fps, W1, b1, W2, b2, W3, b3, image_idx, energy);

    k_scatter<<<(NNZ_ / 4 + 255) / 256, 256>>>(
        (const int4*)fp_rows, (const int4*)fp_cols, (const float4*)fp_vals, force);
}

// round 6
// speedup vs baseline: 1.1342x; 1.0581x over previous
#include <cuda_runtime.h>

// Problem constants (fixed shapes from reference_code)
#define E_    3
#define QE_   60000
#define P_    40
#define H_    20
#define NIMG_ 1800
#define Q_    (E_ * QE_)        // 180000 atoms
#define NNZ_  14400000
#define AB    256               // atoms per block
#define NB    704               // ceil(Q_/AB)
#define OUTSZ (NIMG_ + 3 * Q_)  // 1800 + 1620000... energy + force floats

// Scratch (static device globals — sanctioned)
__device__ float g_dE[(size_t)Q_ * P_];        // NEGATED dE/dFP, sorted order, 28.8 MB
__device__ int   g_hist[(size_t)NIMG_ * NB];
__device__ int   g_key_total[NIMG_];
__device__ int   g_key_base[NIMG_];

__device__ __forceinline__ float tanh_fast(float x) {
    float y;
    asm("tanh.approx.f32 %0, %1;" : "=f"(y) : "f"(x));
    return y;
}

// ---------------------------------------------------------------------------
// Histogram of image_idx, fused with zeroing of the output buffer.
// grid = NB blocks x AB threads; each block also zeros a slice of out.
// ---------------------------------------------------------------------------
__global__ void k_hist(const int* __restrict__ idx,
                       float* __restrict__ out, int out_n) {
    __shared__ int h[NIMG_];
    for (int k = threadIdx.x; k < NIMG_; k += blockDim.x) h[k] = 0;

    // zero out[] (grid-stride slice; no dependence on the histogram)
    for (int i = blockIdx.x * AB + threadIdx.x; i < out_n; i += NB * AB)
        out[i] = 0.0f;
    __syncthreads();

    int a = blockIdx.x * AB + threadIdx.x;
    if (a < Q_) atomicAdd(&h[idx[a]], 1);
    __syncthreads();
    for (int k = threadIdx.x; k < NIMG_; k += blockDim.x)
        g_hist[(size_t)k * NB + blockIdx.x] = h[k];
}

// ---------------------------------------------------------------------------
// Per-key exclusive scan over blocks: warp-shuffle 2-level scan.
// grid = NIMG_, block = 704 (22 warps, exactly NB lanes).
// ---------------------------------------------------------------------------
__global__ void k_scan_blocks() {
    __shared__ int wsum[22];
    int k = blockIdx.x, t = threadIdx.x;
    int lane = t & 31, w = t >> 5;
    int v = g_hist[(size_t)k * NB + t];
    int s = v;
    #pragma unroll
    for (int o = 1; o < 32; o <<= 1) {
        int x = __shfl_up_sync(0xFFFFFFFFu, s, o);
        if (lane >= o) s += x;
    }
    if (lane == 31) wsum[w] = s;
    __syncthreads();
    if (w == 0) {
        int ws = (lane < 22) ? wsum[lane] : 0;
        #pragma unroll
        for (int o = 1; o < 32; o <<= 1) {
            int x = __shfl_up_sync(0xFFFFFFFFu, ws, o);
            if (lane >= o) ws += x;
        }
        if (lane < 22) wsum[lane] = ws;
    }
    __syncthreads();
    int incl = ((w > 0) ? wsum[w - 1] : 0) + s;
    g_hist[(size_t)k * NB + t] = incl - v;   // exclusive
    if (t == NB - 1) g_key_total[k] = incl;
}

// ---------------------------------------------------------------------------
// Exclusive scan over 1800 key totals (2 elems/thread, shuffle scan).
// ---------------------------------------------------------------------------
__global__ void k_scan_keys() {
    __shared__ int wsum[32];
    int t = threadIdx.x, lane = t & 31, w = t >> 5;
    int i0 = 2 * t, i1 = 2 * t + 1;
    int v0 = (i0 < NIMG_) ? g_key_total[i0] : 0;
    int v1 = (i1 < NIMG_) ? g_key_total[i1] : 0;
    int p = v0 + v1, s = p;
    #pragma unroll
    for (int o = 1; o < 32; o <<= 1) {
        int x = __shfl_up_sync(0xFFFFFFFFu, s, o);
        if (lane >= o) s += x;
    }
    if (lane == 31) wsum[w] = s;
    __syncthreads();
    if (w == 0) {
        int ws = wsum[lane];
        #pragma unroll
        for (int o = 1; o < 32; o <<= 1) {
            int x = __shfl_up_sync(0xFFFFFFFFu, ws, o);
            if (lane >= o) ws += x;
        }
        wsum[lane] = ws;
    }
    __syncthreads();
    int excl = ((w > 0) ? wsum[w - 1] : 0) + s - p;
    if (i0 < NIMG_) g_key_base[i0] = excl;
    if (i1 < NIMG_) g_key_base[i1] = excl + v0;
}

// ---------------------------------------------------------------------------
// Fused: stable rank (O(t) smem loop, unrolled) + MLP fwd + input-grad
// + energy scatter. h1/g2/g1 indexed ONLY in fully-unrolled loops.
// ---------------------------------------------------------------------------
__global__ void __launch_bounds__(AB) k_mlp(
    const float* __restrict__ fps, const float* __restrict__ W1,
    const float* __restrict__ b1,  const float* __restrict__ W2,
    const float* __restrict__ b2,  const float* __restrict__ W3,
    const float* __restrict__ b3,  const int* __restrict__ idx,
    float* __restrict__ energy)
{
    __shared__ float sW1[E_ * P_ * H_];
    __shared__ float sB1[E_ * H_];
    __shared__ float sW2[E_ * H_ * H_];
    __shared__ float sB2[E_ * H_];
    __shared__ float sW3[E_ * H_];
    __shared__ float sB3[E_];
    __shared__ int   skey[AB];

    int t = threadIdx.x;
    for (int i = t; i < E_ * P_ * H_; i += AB) sW1[i] = W1[i];
    for (int i = t; i < E_ * H_;      i += AB) sB1[i] = b1[i];
    for (int i = t; i < E_ * H_ * H_; i += AB) sW2[i] = W2[i];
    for (int i = t; i < E_ * H_;      i += AB) sB2[i] = b2[i];
    for (int i = t; i < E_ * H_;      i += AB) sW3[i] = W3[i];
    if (t < E_) sB3[t] = b3[t];

    int a = blockIdx.x * AB + t;
    int key = (a < Q_) ? idx[a] : -1;
    skey[t] = key;
    __syncthreads();
    if (a >= Q_) return;

    // stable local rank: # of earlier same-key atoms in this block
    int lr = 0;
    {
        int j = 0;
        #pragma unroll 4
        for (; j + 4 <= t; j += 4) {
            lr += (skey[j]     == key);
            lr += (skey[j + 1] == key);
            lr += (skey[j + 2] == key);
            lr += (skey[j + 3] == key);
        }
        for (; j < t; j++) lr += (skey[j] == key);
    }
    int pos = g_key_base[key] + g_hist[(size_t)key * NB + blockIdx.x] + lr;

    int e = a / QE_;
    const float* w1 = sW1 + e * P_ * H_;
    const float* w2 = sW2 + e * H_ * H_;
    const float* w3 = sW3 + e * H_;

    float h1[H_];
    #pragma unroll
    for (int h = 0; h < H_; h++) h1[h] = sB1[e * H_ + h];

    // layer 1: stream x as float4
    const float4* xrow = (const float4*)(fps + (size_t)a * P_);
    #pragma unroll 2
    for (int p4 = 0; p4 < P_ / 4; p4++) {
        float4 x = xrow[p4];
        const float* w1p = w1 + p4 * 4 * H_;
        #pragma unroll
        for (int h = 0; h < H_; h++) {
            float s = fmaf(x.x, w1p[h], h1[h]);
            s = fmaf(x.y, w1p[H_ + h], s);
            s = fmaf(x.z, w1p[2 * H_ + h], s);
            h1[h] = fmaf(x.w, w1p[3 * H_ + h], s);
        }
    }
    #pragma unroll
    for (int h = 0; h < H_; h++) h1[h] = tanh_fast(h1[h]);

    // layer 2
    float g2[H_];
    #pragma unroll
    for (int j = 0; j < H_; j++) {
        float s = sB2[e * H_ + j];
        #pragma unroll
        for (int h = 0; h < H_; h++) s = fmaf(h1[h], w2[h * H_ + j], s);
        g2[j] = tanh_fast(s);
    }

    // layer 3 fwd + backward seed
    float en = sB3[e];
    #pragma unroll
    for (int j = 0; j < H_; j++) {
        float v = g2[j];
        en = fmaf(v, w3[j], en);
        g2[j] = w3[j] * (1.0f - v * v);
    }
    atomicAdd(&energy[key], en);

    // g1 = (W2 @ g2) * (1 - h1^2)
    float g1[H_];
    #pragma unroll
    for (int h = 0; h < H_; h++) {
        float s = 0.0f;
        #pragma unroll
        for (int j = 0; j < H_; j++) s = fmaf(w2[h * H_ + j], g2[j], s);
        g1[h] = s * (1.0f - h1[h] * h1[h]);
    }

    // -dE/dx = -(W1 @ g1), float4 stores into sorted position
    float4* dst = (float4*)(g_dE + (size_t)pos * P_);
    #pragma unroll 2
    for (int p4 = 0; p4 < P_ / 4; p4++) {
        const float* w1p = w1 + p4 * 4 * H_;
        float4 o;
        float s0 = 0, s1 = 0, s2 = 0, s3 = 0;
        #pragma unroll
        for (int h = 0; h < H_; h++) {
            s0 = fmaf(w1p[h],          g1[h], s0);
            s1 = fmaf(w1p[H_ + h],     g1[h], s1);
            s2 = fmaf(w1p[2 * H_ + h], g1[h], s2);
            s3 = fmaf(w1p[3 * H_ + h], g1[h], s3);
        }
        o.x = -s0; o.y = -s1; o.z = -s2; o.w = -s3;
        dst[p4] = o;
    }
}

// ---------------------------------------------------------------------------
// Sparse COO transpose-matvec (R3 form — best known): one int4-group/thread,
// __ldcs streaming on COO arrays so g_dE + force stay L2-resident.
// ---------------------------------------------------------------------------
__global__ void k_scatter(const int4* __restrict__ rows,
                          const int4* __restrict__ cols,
                          const float4* __restrict__ vals,
                          float* __restrict__ force)
{
    int i = blockIdx.x * blockDim.x + threadIdx.x;
    if (i >= NNZ_ / 4) return;
    int4   r = __ldcs(&rows[i]);
    int4   c = __ldcs(&cols[i]);
    float4 v = __ldcs(&vals[i]);
    float d0 = __ldg(&g_dE[r.x]);
    float d1 = __ldg(&g_dE[r.y]);
    float d2 = __ldg(&g_dE[r.z]);
    float d3 = __ldg(&g_dE[r.w]);
    atomicAdd(&force[c.x], v.x * d0);
    atomicAdd(&force[c.y], v.y * d1);
    atomicAdd(&force[c.z], v.z * d2);
    atomicAdd(&force[c.w], v.w * d3);
}

// ---------------------------------------------------------------------------
extern "C" void kernel_launch(void* const* d_in, const int* in_sizes, int n_in,
                              void* d_out, int out_size)
{
    const float* fps       = (const float*)d_in[0];
    const float* W1        = (const float*)d_in[1];
    const float* b1        = (const float*)d_in[2];
    const float* W2        = (const float*)d_in[3];
    const float* b2        = (const float*)d_in[4];
    const float* W3        = (const float*)d_in[5];
    const float* b3        = (const float*)d_in[6];
    const int*   image_idx = (const int*)d_in[7];
    const int*   fp_rows   = (const int*)d_in[8];
    const int*   fp_cols   = (const int*)d_in[9];
    const float* fp_vals   = (const float*)d_in[10];

    float* out    = (float*)d_out;
    float* energy = out;               // [NIMG, 1]
    float* force  = out + NIMG_;       // [Q, 3] flattened

    // hist + output zeroing fused
    k_hist<<<NB, AB>>>(image_idx, out, out_size);
    k_scan_blocks<<<NIMG_, NB>>>();
    k_scan_keys<<<1, 1024>>>();

    k_mlp<<<NB, AB>>>(fps, W1, b1, W2, b2, W3, b3, image_idx, energy);

    k_scatter<<<(NNZ_ / 4 + 255) / 256, 256>>>(
        (const int4*)fp_rows, (const int4*)fp_cols, (const float4*)fp_vals, force);
}